// round 1
// baseline (speedup 1.0000x reference)
#include <cuda_runtime.h>
#include <cuda_bf16.h>
#include <cstdint>

// Problem constants
#define B_  16
#define C_  256
#define HW_ 4096          // 64*64
#define H_  64
#define W_  64
#define K_  7
#define KK_ 49
#define CR_ 64            // C/4
#define CKK_ 12544        // C*49

// ---------------- scratch (device globals; no allocation allowed) -------------
__device__ float g_pooled[B_ * C_];            // [B,C]
__device__ float g_h[B_ * CR_];                // [B,C/4]
__device__ float g_fused[B_ * CKK_];           // [B, C*49]
__device__ float g_tmp[(size_t)B_ * C_ * HW_]; // 64 MB depthwise output

// ============================================================================
// Kernel A: global average pool.  grid = B*C blocks, 256 threads.
// ============================================================================
__global__ __launch_bounds__(256) void pool_kernel(const float* __restrict__ x) {
    int bc = blockIdx.x;
    const float* xp = x + (size_t)bc * HW_;
    int tid = threadIdx.x;
    float s = 0.f;
#pragma unroll
    for (int i = 0; i < HW_ / 256; i++) s += xp[tid + i * 256];
    // warp reduce
#pragma unroll
    for (int o = 16; o > 0; o >>= 1) s += __shfl_down_sync(0xffffffffu, s, o);
    __shared__ float red[8];
    if ((tid & 31) == 0) red[tid >> 5] = s;
    __syncthreads();
    if (tid == 0) {
        float t = 0.f;
#pragma unroll
        for (int i = 0; i < 8; i++) t += red[i];
        g_pooled[bc] = t * (1.0f / HW_);
    }
}

// ============================================================================
// Kernel B: h = gelu(pooled @ w1^T + b1).  grid = B blocks, 64 threads.
// w1: [C/4, C] row-major.
// ============================================================================
__global__ __launch_bounds__(64) void mlp1_kernel(const float* __restrict__ w1,
                                                  const float* __restrict__ b1) {
    int b = blockIdx.x;
    int j = threadIdx.x;
    __shared__ float sp[C_];
#pragma unroll
    for (int i = 0; i < C_ / 64; i++) sp[j + i * 64] = g_pooled[b * C_ + j + i * 64];
    __syncthreads();
    const float* wr = w1 + j * C_;
    float s = 0.f;
#pragma unroll 8
    for (int i = 0; i < C_; i++) s = fmaf(sp[i], wr[i], s);
    float z = s + b1[j];
    // exact gelu
    float g = 0.5f * z * (1.0f + erff(z * 0.70710678118654752440f));
    g_h[b * CR_ + j] = g;
}

// ============================================================================
// Kernel C: fused[b, c*49+t] = dw[c*49+t] + (h[b] @ w2^T + b2)[c*49+t]
// grid = B*49 blocks of 256 threads (49*256 = 12544 exactly per sample).
// w2: [12544, 64] row-major.
// ============================================================================
__global__ __launch_bounds__(256) void weights_kernel(const float* __restrict__ dw,
                                                      const float* __restrict__ w2,
                                                      const float* __restrict__ b2) {
    int b = blockIdx.x / 49;
    int chunk = blockIdx.x % 49;
    int ck = chunk * 256 + threadIdx.x; // 0..12543
    __shared__ float sh[CR_];
    if (threadIdx.x < CR_) sh[threadIdx.x] = g_h[b * CR_ + threadIdx.x];
    __syncthreads();
    const float* wr = w2 + (size_t)ck * CR_;
    float s = 0.f;
#pragma unroll
    for (int i = 0; i < CR_; i++) s = fmaf(sh[i], wr[i], s);
    g_fused[b * CKK_ + ck] = s + b2[ck] + dw[ck];
}

// ============================================================================
// Kernel D: depthwise 7x7 conv, pad 3.  grid = B*C blocks, 256 threads.
// Each thread computes a 1x16 horizontal strip via register sliding window.
// ============================================================================
__global__ __launch_bounds__(256) void dwconv_kernel(const float* __restrict__ x) {
    int bc = blockIdx.x;
    const float* xp = x + (size_t)bc * HW_;
    float* op = g_tmp + (size_t)bc * HW_;
    int tid = threadIdx.x;

    __shared__ float sx[H_ * (W_ + 1)]; // stride 65 to dodge conflicts
    __shared__ float sw[KK_];

#pragma unroll
    for (int i = 0; i < HW_ / 256; i++) {
        int idx = tid + i * 256;
        sx[(idx >> 6) * (W_ + 1) + (idx & 63)] = xp[idx];
    }
    if (tid < KK_) sw[tid] = g_fused[bc * KK_ + tid];
    __syncthreads();

    int r    = tid >> 2;        // output row 0..63
    int col0 = (tid & 3) * 16;  // output col start

    float acc[16];
#pragma unroll
    for (int j = 0; j < 16; j++) acc[j] = 0.f;

#pragma unroll
    for (int ky = 0; ky < 7; ky++) {
        int ry = r + ky - 3;
        if (ry < 0 || ry >= H_) continue;
        float v[22];
#pragma unroll
        for (int t = 0; t < 22; t++) {
            int cc = col0 - 3 + t;
            v[t] = (cc >= 0 && cc < W_) ? sx[ry * (W_ + 1) + cc] : 0.f;
        }
#pragma unroll
        for (int kx = 0; kx < 7; kx++) {
            float wv = sw[ky * 7 + kx];
#pragma unroll
            for (int j = 0; j < 16; j++) acc[j] = fmaf(wv, v[j + kx], acc[j]);
        }
    }
#pragma unroll
    for (int j = 0; j < 16; j++) op[r * W_ + col0 + j] = acc[j];
}

// ============================================================================
// Kernel E: pointwise GEMM on tf32 tensor cores.
// Per b: Y[o, p] = sum_c P[o,c] * T[c,p].  M=256, N=4096, K=256.
// Block tile 128x128, BK=32, 8 warps (warp tile 64x32), mma.m16n8k8 tf32.
// ============================================================================
#define BM 128
#define BN 128
#define BK 32
#define AS_STRIDE 36   // BK + 4 pad
#define BS_STRIDE 132  // BN + 4 pad

__device__ __forceinline__ uint32_t f2tf32(float x) {
    uint32_t u;
    asm("cvt.rna.tf32.f32 %0, %1;" : "=r"(u) : "f"(x));
    return u;
}

__global__ __launch_bounds__(256) void pw_gemm_kernel(const float* __restrict__ P,
                                                      float* __restrict__ Y) {
    __shared__ float As[BM * AS_STRIDE]; // As[m][k], values pre-rounded to tf32
    __shared__ float Bs[BK * BS_STRIDE]; // Bs[k][n]

    int bn = blockIdx.x;          // 0..31
    int bm = blockIdx.y;          // 0..1
    int b  = blockIdx.z;          // 0..15

    int tid  = threadIdx.x;
    int lane = tid & 31;
    int wid  = tid >> 5;
    int wm = (wid & 1) * 64;
    int wn = (wid >> 1) * 32;
    int g   = lane >> 2;
    int tig = lane & 3;

    const float* Pg = P + (size_t)(bm * BM) * C_;
    const float* Tg = g_tmp + ((size_t)b * C_) * HW_ + bn * BN;
    float*       Yg = Y + ((size_t)b * C_ + bm * BM) * HW_ + bn * BN;

    float acc[4][4][4];
#pragma unroll
    for (int im = 0; im < 4; im++)
#pragma unroll
        for (int in = 0; in < 4; in++)
#pragma unroll
            for (int q = 0; q < 4; q++) acc[im][in][q] = 0.f;

    for (int kc = 0; kc < C_ / BK; kc++) {
        int k0 = kc * BK;
        // load A tile (P): 128x32
#pragma unroll
        for (int t = 0; t < (BM * BK) / 256; t++) {
            int i = tid + t * 256;
            int m = i >> 5, k = i & 31;
            As[m * AS_STRIDE + k] = __uint_as_float(f2tf32(Pg[m * C_ + k0 + k]));
        }
        // load B tile (T): 32x128
#pragma unroll
        for (int t = 0; t < (BK * BN) / 256; t++) {
            int i = tid + t * 256;
            int k = i >> 7, n = i & 127;
            Bs[k * BS_STRIDE + n] = __uint_as_float(f2tf32(Tg[(size_t)(k0 + k) * HW_ + n]));
        }
        __syncthreads();

#pragma unroll
        for (int ks = 0; ks < BK / 8; ks++) {
            int kk = ks * 8;
            uint32_t a[4][4], bf[4][2];
#pragma unroll
            for (int im = 0; im < 4; im++) {
                int r0 = wm + im * 16 + g;
                a[im][0] = __float_as_uint(As[r0 * AS_STRIDE + kk + tig]);
                a[im][1] = __float_as_uint(As[(r0 + 8) * AS_STRIDE + kk + tig]);
                a[im][2] = __float_as_uint(As[r0 * AS_STRIDE + kk + tig + 4]);
                a[im][3] = __float_as_uint(As[(r0 + 8) * AS_STRIDE + kk + tig + 4]);
            }
#pragma unroll
            for (int in = 0; in < 4; in++) {
                int cc = wn + in * 8 + g;
                bf[in][0] = __float_as_uint(Bs[(kk + tig) * BS_STRIDE + cc]);
                bf[in][1] = __float_as_uint(Bs[(kk + tig + 4) * BS_STRIDE + cc]);
            }
#pragma unroll
            for (int im = 0; im < 4; im++)
#pragma unroll
                for (int in = 0; in < 4; in++) {
                    asm volatile(
                        "mma.sync.aligned.m16n8k8.row.col.f32.tf32.tf32.f32 "
                        "{%0,%1,%2,%3}, {%4,%5,%6,%7}, {%8,%9}, {%0,%1,%2,%3};"
                        : "+f"(acc[im][in][0]), "+f"(acc[im][in][1]),
                          "+f"(acc[im][in][2]), "+f"(acc[im][in][3])
                        : "r"(a[im][0]), "r"(a[im][1]), "r"(a[im][2]), "r"(a[im][3]),
                          "r"(bf[in][0]), "r"(bf[in][1]));
                }
        }
        __syncthreads();
    }

    // epilogue
#pragma unroll
    for (int im = 0; im < 4; im++) {
#pragma unroll
        for (int in = 0; in < 4; in++) {
            int row = wm + im * 16 + g;
            int cc  = wn + in * 8 + tig * 2;
            float2 v0 = make_float2(acc[im][in][0], acc[im][in][1]);
            float2 v1 = make_float2(acc[im][in][2], acc[im][in][3]);
            *reinterpret_cast<float2*>(&Yg[(size_t)row * HW_ + cc])       = v0;
            *reinterpret_cast<float2*>(&Yg[(size_t)(row + 8) * HW_ + cc]) = v1;
        }
    }
}

// ============================================================================
// launcher
// ============================================================================
extern "C" void kernel_launch(void* const* d_in, const int* in_sizes, int n_in,
                              void* d_out, int out_size) {
    const float* x  = (const float*)d_in[0]; // [16,256,64,64]
    const float* dw = (const float*)d_in[1]; // [256,1,7,7]
    const float* pw = (const float*)d_in[2]; // [256,256]
    const float* w1 = (const float*)d_in[3]; // [64,256]
    const float* b1 = (const float*)d_in[4]; // [64]
    const float* w2 = (const float*)d_in[5]; // [12544,64]
    const float* b2 = (const float*)d_in[6]; // [12544]
    float* y = (float*)d_out;

    pool_kernel<<<B_ * C_, 256>>>(x);
    mlp1_kernel<<<B_, 64>>>(w1, b1);
    weights_kernel<<<B_ * 49, 256>>>(dw, w2, b2);
    dwconv_kernel<<<B_ * C_, 256>>>(x);
    dim3 ggrid(HW_ / BN, C_ / BM, B_);
    pw_gemm_kernel<<<ggrid, 256>>>(pw, y);
}

// round 5
// speedup vs baseline: 2.0544x; 2.0544x over previous
#include <cuda_runtime.h>
#include <cuda_bf16.h>
#include <cstdint>

#define B_  16
#define C_  256
#define HW_ 4096
#define H_  64
#define W_  64
#define KK_ 49
#define CR_ 64
#define CKK_ 12544

// ---------------- scratch ----------------
__device__ float g_pooled[B_ * C_];
__device__ float g_h[B_ * CR_];
__device__ float g_fused[B_ * CKK_];
__device__ float g_pw[C_ * C_];                 // tf32-rounded pointwise weights
__device__ float g_tmp[(size_t)B_ * C_ * HW_];  // tf32-rounded depthwise output

__device__ __forceinline__ uint32_t f2tf32(float x) {
    uint32_t u; asm("cvt.rna.tf32.f32 %0, %1;" : "=r"(u) : "f"(x)); return u;
}
// packed f32x2 helpers — b64 regs via "l" constraint
__device__ __forceinline__ uint64_t pkd(float x, float y) {
    uint64_t d; asm("mov.b64 %0, {%1,%2};" : "=l"(d) : "f"(x), "f"(y)); return d;
}
__device__ __forceinline__ void fma2(uint64_t& acc, uint64_t a, uint64_t b) {
    asm("fma.rn.f32x2 %0, %1, %2, %0;" : "+l"(acc) : "l"(a), "l"(b));
}
__device__ __forceinline__ void unpk(uint64_t d, float& x, float& y) {
    asm("mov.b64 {%0,%1}, %2;" : "=f"(x), "=f"(y) : "l"(d));
}

// ============================================================================
// Kernel A: global average pool
// ============================================================================
__global__ __launch_bounds__(256) void pool_kernel(const float* __restrict__ x) {
    int bc = blockIdx.x;
    const float* xp = x + (size_t)bc * HW_;
    int tid = threadIdx.x;
    float s = 0.f;
#pragma unroll
    for (int i = 0; i < HW_ / 256; i++) s += xp[tid + i * 256];
#pragma unroll
    for (int o = 16; o > 0; o >>= 1) s += __shfl_down_sync(0xffffffffu, s, o);
    __shared__ float red[8];
    if ((tid & 31) == 0) red[tid >> 5] = s;
    __syncthreads();
    if (tid == 0) {
        float t = 0.f;
#pragma unroll
        for (int i = 0; i < 8; i++) t += red[i];
        g_pooled[bc] = t * (1.0f / HW_);
    }
}

// ============================================================================
// Kernel B: h = gelu(pooled @ w1^T + b1)
// ============================================================================
__global__ __launch_bounds__(64) void mlp1_kernel(const float* __restrict__ w1,
                                                  const float* __restrict__ b1) {
    int b = blockIdx.x, j = threadIdx.x;
    __shared__ float sp[C_];
#pragma unroll
    for (int i = 0; i < C_ / 64; i++) sp[j + i * 64] = g_pooled[b * C_ + j + i * 64];
    __syncthreads();
    const float* wr = w1 + j * C_;
    float s = 0.f;
#pragma unroll 8
    for (int i = 0; i < C_; i++) s = fmaf(sp[i], wr[i], s);
    float z = s + b1[j];
    g_h[b * CR_ + j] = 0.5f * z * (1.0f + erff(z * 0.70710678118654752440f));
}

// ============================================================================
// Kernel C: fused dynamic weights
// ============================================================================
__global__ __launch_bounds__(256) void weights_kernel(const float* __restrict__ dw,
                                                      const float* __restrict__ w2,
                                                      const float* __restrict__ b2) {
    int b = blockIdx.x / 49;
    int ck = (blockIdx.x % 49) * 256 + threadIdx.x;
    __shared__ float sh[CR_];
    if (threadIdx.x < CR_) sh[threadIdx.x] = g_h[b * CR_ + threadIdx.x];
    __syncthreads();
    const float* wr = w2 + (size_t)ck * CR_;
    float s = 0.f;
#pragma unroll
    for (int i = 0; i < CR_; i++) s = fmaf(sh[i], wr[i], s);
    g_fused[b * CKK_ + ck] = s + b2[ck] + dw[ck];
}

// ============================================================================
// Kernel C2: round pointwise weights to tf32 once
// ============================================================================
__global__ __launch_bounds__(256) void round_pw_kernel(const float* __restrict__ pw) {
    int i = blockIdx.x * 256 + threadIdx.x;
    g_pw[i] = __uint_as_float(f2tf32(pw[i]));
}

// ============================================================================
// Kernel D: depthwise 7x7 conv with packed f32x2 FMA.
// ============================================================================
#define DSTR 72
__global__ __launch_bounds__(128) void dwconv2_kernel(const float* __restrict__ x) {
    __shared__ __align__(16) float sA[H_ * DSTR];
    __shared__ __align__(16) float sB[H_ * DSTR];
    __shared__ float sw[KK_];

    int bc = blockIdx.x;
    const float* xp = x + (size_t)bc * HW_;
    int tid = threadIdx.x;

#pragma unroll
    for (int i = 0; i < 9; i++) {
        ((float4*)sA)[tid + i * 128] = make_float4(0.f, 0.f, 0.f, 0.f);
        ((float4*)sB)[tid + i * 128] = make_float4(0.f, 0.f, 0.f, 0.f);
    }
    if (tid < KK_) sw[tid] = g_fused[bc * KK_ + tid];
    __syncthreads();

#pragma unroll
    for (int i = 0; i < 8; i++) {
        int lin = tid + i * 128;
        int row = lin >> 4, c4 = (lin & 15) << 2;
        float4 v = ((const float4*)xp)[lin];
        float* a = sA + row * DSTR + c4;
        a[3] = v.x; a[4] = v.y; a[5] = v.z; a[6] = v.w;
        float* b = sB + row * DSTR + c4;
        b[2] = v.x; b[3] = v.y; b[4] = v.z; b[5] = v.w;
    }
    __syncthreads();

    uint64_t wp[KK_];
#pragma unroll
    for (int k = 0; k < KK_; k++) { float w = sw[k]; wp[k] = pkd(w, w); }

    int wid = tid >> 5, L = tid & 31;
    int r0 = wid << 4;

    uint64_t acc[16];
#pragma unroll
    for (int r = 0; r < 16; r++) acc[r] = 0ull;

#pragma unroll
    for (int iyr = -3; iyr <= 18; iyr++) {
        int iy = r0 + iyr;
        bool vld = (iy >= 0 && iy < H_);
        int iyc = vld ? iy : 0;
        const uint64_t* pA = (const uint64_t*)(sA + iyc * DSTR) + L;
        const uint64_t* pB = (const uint64_t*)(sB + iyc * DSTR) + L;
        uint64_t pa0 = vld ? pA[0] : 0ull;
        uint64_t pa1 = vld ? pA[1] : 0ull;
        uint64_t pa2 = vld ? pA[2] : 0ull;
        uint64_t pa3 = vld ? pA[3] : 0ull;
        uint64_t pb0 = vld ? pB[0] : 0ull;
        uint64_t pb1 = vld ? pB[1] : 0ull;
        uint64_t pb2 = vld ? pB[2] : 0ull;
#pragma unroll
        for (int ky = 0; ky < 7; ky++) {
            int rr = iyr + 3 - ky;
            if (rr < 0 || rr > 15) continue;
            const int wb = ky * 7;
            fma2(acc[rr], wp[wb + 0], pa0);
            fma2(acc[rr], wp[wb + 1], pb0);
            fma2(acc[rr], wp[wb + 2], pa1);
            fma2(acc[rr], wp[wb + 3], pb1);
            fma2(acc[rr], wp[wb + 4], pa2);
            fma2(acc[rr], wp[wb + 5], pb2);
            fma2(acc[rr], wp[wb + 6], pa3);
        }
    }

    float* op = g_tmp + (size_t)bc * HW_;
#pragma unroll
    for (int rr = 0; rr < 16; rr++) {
        float f0, f1; unpk(acc[rr], f0, f1);
        float2 o;
        o.x = __uint_as_float(f2tf32(f0));
        o.y = __uint_as_float(f2tf32(f1));
        ((float2*)(op + (r0 + rr) * W_))[L] = o;
    }
}

// ============================================================================
// Kernel E: tf32 tensor-core GEMM, cp.async double-buffered.
// ============================================================================
#define BM 128
#define BN 128
#define BK 16
#define ASTR 20    // BK + 4
#define BSTR 132   // BN + 4

__device__ __forceinline__ void cpa16(void* s, const void* g) {
    unsigned sa = (unsigned)__cvta_generic_to_shared(s);
    asm volatile("cp.async.cg.shared.global [%0], [%1], 16;\n" :: "r"(sa), "l"(g));
}
__device__ __forceinline__ void cpcommit() { asm volatile("cp.async.commit_group;\n"); }
template<int N> __device__ __forceinline__ void cpwait() {
    asm volatile("cp.async.wait_group %0;\n" :: "n"(N));
}

__global__ __launch_bounds__(128) void pw_gemm_kernel(float* __restrict__ Y) {
    __shared__ float As[2][BM * ASTR];
    __shared__ float Bs[2][BK * BSTR];

    int bn = blockIdx.x, bm = blockIdx.y, b = blockIdx.z;
    int tid = threadIdx.x, lane = tid & 31, wid = tid >> 5;
    int wm = (wid & 1) * 64, wn = (wid >> 1) * 64;
    int g = lane >> 2, tig = lane & 3;

    const float* Pg = g_pw + (size_t)(bm * BM) * C_;
    const float* Tg = g_tmp + ((size_t)b * C_) * HW_ + bn * BN;
    float*       Yg = Y + ((size_t)b * C_ + bm * BM) * HW_ + bn * BN;

    // per-thread cp.async chunk coords
    int arow0 = tid >> 2, ac = (tid & 3) << 2;    // A: 4 passes of 32 rows
    int brow0 = tid >> 5, bc16 = (tid & 31) << 2; // B: 4 passes of 4 rows

    float acc[4][8][4];
#pragma unroll
    for (int im = 0; im < 4; im++)
#pragma unroll
        for (int in = 0; in < 8; in++)
#pragma unroll
            for (int q = 0; q < 4; q++) acc[im][in][q] = 0.f;

    // prefetch tile 0
    {
#pragma unroll
        for (int t = 0; t < 4; t++) {
            int m = arow0 + t * 32;
            cpa16(&As[0][m * ASTR + ac], Pg + (size_t)m * C_ + ac);
        }
#pragma unroll
        for (int t = 0; t < 4; t++) {
            int r = brow0 + t * 4;
            cpa16(&Bs[0][r * BSTR + bc16], Tg + (size_t)r * HW_ + bc16);
        }
        cpcommit();
    }

    for (int kc = 0; kc < C_ / BK; kc++) {
        int cur = kc & 1;
        if (kc < C_ / BK - 1) {
            int nxt = cur ^ 1, k0 = (kc + 1) * BK;
#pragma unroll
            for (int t = 0; t < 4; t++) {
                int m = arow0 + t * 32;
                cpa16(&As[nxt][m * ASTR + ac], Pg + (size_t)m * C_ + k0 + ac);
            }
#pragma unroll
            for (int t = 0; t < 4; t++) {
                int r = brow0 + t * 4;
                cpa16(&Bs[nxt][r * BSTR + bc16], Tg + (size_t)(k0 + r) * HW_ + bc16);
            }
            cpcommit();
            cpwait<1>();
        } else {
            cpwait<0>();
        }
        __syncthreads();

#pragma unroll
        for (int ks = 0; ks < BK / 8; ks++) {
            int kk = ks * 8;
            uint32_t a[4][4], bf[8][2];
#pragma unroll
            for (int im = 0; im < 4; im++) {
                int r0 = wm + im * 16 + g;
                a[im][0] = __float_as_uint(As[cur][r0 * ASTR + kk + tig]);
                a[im][1] = __float_as_uint(As[cur][(r0 + 8) * ASTR + kk + tig]);
                a[im][2] = __float_as_uint(As[cur][r0 * ASTR + kk + tig + 4]);
                a[im][3] = __float_as_uint(As[cur][(r0 + 8) * ASTR + kk + tig + 4]);
            }
#pragma unroll
            for (int in = 0; in < 8; in++) {
                int cc = wn + in * 8 + g;
                bf[in][0] = __float_as_uint(Bs[cur][(kk + tig) * BSTR + cc]);
                bf[in][1] = __float_as_uint(Bs[cur][(kk + tig + 4) * BSTR + cc]);
            }
#pragma unroll
            for (int im = 0; im < 4; im++)
#pragma unroll
                for (int in = 0; in < 8; in++) {
                    asm volatile(
                        "mma.sync.aligned.m16n8k8.row.col.f32.tf32.tf32.f32 "
                        "{%0,%1,%2,%3}, {%4,%5,%6,%7}, {%8,%9}, {%0,%1,%2,%3};"
                        : "+f"(acc[im][in][0]), "+f"(acc[im][in][1]),
                          "+f"(acc[im][in][2]), "+f"(acc[im][in][3])
                        : "r"(a[im][0]), "r"(a[im][1]), "r"(a[im][2]), "r"(a[im][3]),
                          "r"(bf[in][0]), "r"(bf[in][1]));
                }
        }
        __syncthreads();
    }

#pragma unroll
    for (int im = 0; im < 4; im++) {
#pragma unroll
        for (int in = 0; in < 8; in++) {
            int row = wm + im * 16 + g;
            int cc  = wn + in * 8 + tig * 2;
            float2 v0 = make_float2(acc[im][in][0], acc[im][in][1]);
            float2 v1 = make_float2(acc[im][in][2], acc[im][in][3]);
            *reinterpret_cast<float2*>(&Yg[(size_t)row * HW_ + cc])       = v0;
            *reinterpret_cast<float2*>(&Yg[(size_t)(row + 8) * HW_ + cc]) = v1;
        }
    }
}

// ============================================================================
// launcher
// ============================================================================
extern "C" void kernel_launch(void* const* d_in, const int* in_sizes, int n_in,
                              void* d_out, int out_size) {
    const float* x  = (const float*)d_in[0];
    const float* dw = (const float*)d_in[1];
    const float* pw = (const float*)d_in[2];
    const float* w1 = (const float*)d_in[3];
    const float* b1 = (const float*)d_in[4];
    const float* w2 = (const float*)d_in[5];
    const float* b2 = (const float*)d_in[6];
    float* y = (float*)d_out;

    pool_kernel<<<B_ * C_, 256>>>(x);
    round_pw_kernel<<<C_ * C_ / 256, 256>>>(pw);
    mlp1_kernel<<<B_, 64>>>(w1, b1);
    weights_kernel<<<B_ * 49, 256>>>(dw, w2, b2);
    dwconv2_kernel<<<B_ * C_, 128>>>(x);
    dim3 ggrid(HW_ / BN, C_ / BM, B_);
    pw_gemm_kernel<<<ggrid, 128>>>(y);
}